// round 10
// baseline (speedup 1.0000x reference)
#include <cuda_runtime.h>

// Problem shapes (fixed by the dataset)
#define NB 16        // batch
#define NC 3         // channels
#define TH 512       // tex H
#define TW 512       // tex W
#define OH 768       // out H
#define OW 768       // out W
#define NI 25        // lut dim 0 (part index)
#define LD 256       // lut dims 1,2
#define TD 25        // table coverage for vi/ui (data has values in [0,25))

#define TEX_PLANE (TH*TW)          // 262144
#define TEX_IMG   (NC*TEX_PLANE)   // 786432
#define OUT_PLANE (OH*OW)          // 589824
#define OUT_IMG   (NC*OUT_PLANE)   // 1769472
#define TBL_PER_B (NI*TD*TD)       // 15625
#define PST_RG    15626            // float2 plane stride (pad even -> 125008 B)
#define PST_B     15628            // float plane stride (pad /4 -> 62512 B)

#define CTAS_PER_B 9               // 589824 = 9 * 65536 -> 144 CTAs = one wave
#define QUADS_PER_CTA 16384        // 65536 pixels / 4
#define MAP_THREADS 1024

// Precomputed sample table: float2 rg plane + float b plane (~3 MB, L2-resident)
__device__ float2 g_tab_rg[NB * PST_RG];
__device__ float  g_tab_b [NB * PST_B];

// ---------------------------------------------------------------------------
// Variant A (map_pixels' inline fallback — branchy, exact R4/R9 form):
// bilinear grid-sample matching torch grid_sample (bilinear, zeros,
// align_corners=True).
__device__ __forceinline__ float3 sample_tex_branchy(const float* __restrict__ tex,
                                                     int b, float us, float vs) {
    float uI = us * 2.0f - 1.0f;
    float vI = (1.0f - vs) * 2.0f - 1.0f;
    float x = (uI + 1.0f) * 0.5f * (float)(TW - 1);
    float y = (vI + 1.0f) * 0.5f * (float)(TH - 1);
    float x0f = floorf(x);
    float y0f = floorf(y);
    float wx = x - x0f;
    float wy = y - y0f;
    int x0 = (int)x0f;
    int y0 = (int)y0f;

    const float* __restrict__ base = tex + (size_t)b * TEX_IMG;
    float r = 0.0f, g = 0.0f, bl = 0.0f;
#pragma unroll
    for (int dy = 0; dy < 2; dy++) {
#pragma unroll
        for (int dx = 0; dx < 2; dx++) {
            int xx = x0 + dx;
            int yy = y0 + dy;
            bool valid = (xx >= 0) & (xx < TW) & (yy >= 0) & (yy < TH);
            float w = (dy ? wy : (1.0f - wy)) * (dx ? wx : (1.0f - wx));
            if (valid) {
                int off = yy * TW + xx;
                r  += __ldg(base + off) * w;
                g  += __ldg(base + TEX_PLANE + off) * w;
                bl += __ldg(base + 2 * TEX_PLANE + off) * w;
            }
        }
    }
    return make_float3(r, g, bl);
}

// Variant B (build_table — branchless, exact R6/R9 form): loads always issue
// from clamped addresses; validity folded into the weight so ptxas can
// front-batch all 12 LDGs per entry.
__device__ __forceinline__ float3 sample_tex_nobranch(const float* __restrict__ tex,
                                                      int b, float us, float vs) {
    float uI = us * 2.0f - 1.0f;
    float vI = (1.0f - vs) * 2.0f - 1.0f;
    float x = (uI + 1.0f) * 0.5f * (float)(TW - 1);
    float y = (vI + 1.0f) * 0.5f * (float)(TH - 1);
    float x0f = floorf(x);
    float y0f = floorf(y);
    float wx = x - x0f;
    float wy = y - y0f;
    int x0 = (int)x0f;
    int y0 = (int)y0f;

    const float* __restrict__ base = tex + (size_t)b * TEX_IMG;
    float r = 0.0f, g = 0.0f, bl = 0.0f;

    float tr[4], tg[4], tb[4], wq[4];
#pragma unroll
    for (int dy = 0; dy < 2; dy++) {
#pragma unroll
        for (int dx = 0; dx < 2; dx++) {
            int k = dy * 2 + dx;
            int xx = x0 + dx;
            int yy = y0 + dy;
            bool valid = (xx >= 0) & (xx < TW) & (yy >= 0) & (yy < TH);
            float w = (dy ? wy : (1.0f - wy)) * (dx ? wx : (1.0f - wx));
            wq[k] = valid ? w : 0.0f;
            int off = min(max(yy, 0), TH - 1) * TW + min(max(xx, 0), TW - 1);
            tr[k] = __ldg(base + off);
            tg[k] = __ldg(base + TEX_PLANE + off);
            tb[k] = __ldg(base + 2 * TEX_PLANE + off);
        }
    }
#pragma unroll
    for (int k = 0; k < 4; k++) {
        r  += tr[k] * wq[k];
        g  += tg[k] * wq[k];
        bl += tb[k] * wq[k];
    }
    return make_float3(r, g, bl);
}

// Phase 1: build the (b, i, vi, ui) -> rgb table. 4 entries per thread
// (grid-strided by quarter) so ~48 independent gathers overlap per thread.
#define BT_THREADS 256
#define BT_QUARTER (NB * TBL_PER_B / 4)      // 62500
__global__ void __launch_bounds__(BT_THREADS)
build_table(const float* __restrict__ tex, const float* __restrict__ lut) {
    int t = blockIdx.x * blockDim.x + threadIdx.x;
    if (t >= BT_QUARTER) return;

    int eb[4], er[4];
    float us[4], vs[4];
#pragma unroll
    for (int h = 0; h < 4; h++) {
        int e = t + h * BT_QUARTER;
        int b  = e / TBL_PER_B;
        int r  = e - b * TBL_PER_B;
        int i  = r / (TD * TD);
        int r2 = r - i * (TD * TD);
        int vi = r2 / TD;
        int ui = r2 - vi * TD;
        int lo = ((i * LD + vi) * LD + ui) * 2;
        us[h] = __ldg(lut + lo);
        vs[h] = __ldg(lut + lo + 1);
        eb[h] = b; er[h] = r;
    }
#pragma unroll
    for (int h = 0; h < 4; h++) {
        float3 c = sample_tex_nobranch(tex, eb[h], us[h], vs[h]);
        g_tab_rg[eb[h] * PST_RG + er[h]] = make_float2(c.x, c.y);
        g_tab_b [eb[h] * PST_B  + er[h]] = c.z;
    }
}

// Per-pixel fast path: table index from clamped ints; fallback (inline,
// branchy) for ui/vi >= TD -- never taken on this data, kept for generality.
// For int32 inputs, rint(clip(ua/255,0,1)*255) == clamp(ua,0,255) exactly.
__device__ __forceinline__ void lookup_px(int ia, int ua, int va,
                                          const float2* __restrict__ srg,
                                          const float* __restrict__ sb,
                                          const float* __restrict__ tex,
                                          const float* __restrict__ lut,
                                          int b, float& r, float& g, float& bl) {
    int i  = min(max(ia, 0), NI - 1);
    int ui = min(max(ua, 0), LD - 1);
    int vi = min(max(va, 0), LD - 1);
    if (ui < TD && vi < TD) {
        int idx = (i * TD + vi) * TD + ui;
        float2 rg = srg[idx];
        r = rg.x; g = rg.y; bl = sb[idx];
    } else {
        int lo = ((i * LD + vi) * LD + ui) * 2;
        float3 c = sample_tex_branchy(tex, b, lut[lo], lut[lo + 1]);
        r = c.x; g = c.y; bl = c.z;
    }
}

// Phase 2: streaming pass with fp32 table slice staged in shared memory.
// ~187.5 KB smem/CTA -> 1 CTA/SM, 144 CTAs = one full wave.
// Loop structure identical to the proven R4/R9 kernel; only the table layout
// changed (2 smem loads per pixel instead of 3).
__global__ void __launch_bounds__(MAP_THREADS, 1)
map_pixels(const float* __restrict__ tex,
           const int* __restrict__ iuv,
           const float* __restrict__ lut,
           float* __restrict__ out) {
    extern __shared__ char smem[];
    float2* srg = (float2*)smem;                         // 15626*8 = 125008 B
    float*  sb  = (float*)(smem + PST_RG * 8);           // 15628*4 =  62512 B

    int b   = blockIdx.x / CTAS_PER_B;
    int sub = blockIdx.x - b * CTAS_PER_B;
    int tid = threadIdx.x;

    // Stage this batch's table slice into smem (float4 bulk copy).
    {
        const float4* src = (const float4*)&g_tab_rg[b * PST_RG];
        float4* dst = (float4*)srg;
        for (int t = tid; t < (PST_RG * 8) / 16; t += MAP_THREADS)
            dst[t] = src[t];
        const float4* src2 = (const float4*)&g_tab_b[b * PST_B];
        float4* dst2 = (float4*)sb;
        for (int t = tid; t < (PST_B * 4) / 16; t += MAP_THREADS)
            dst2[t] = src2[t];
    }
    __syncthreads();

    const int* __restrict__ ib = iuv + (size_t)b * OUT_IMG;
    float* __restrict__ ob = out + (size_t)b * OUT_IMG;
    const int q0 = sub * QUADS_PER_CTA;

    // 2 quads (8 pixels) per iteration: 6 front-batched int4 loads for MLP.
#pragma unroll
    for (int j = 0; j < QUADS_PER_CTA / (2 * MAP_THREADS); j++) {
        int qa = q0 + j * (2 * MAP_THREADS) + tid;
        int qb = qa + MAP_THREADS;

        int4 iA = ((const int4*)(ib))[qa];
        int4 iB = ((const int4*)(ib))[qb];
        int4 uA = ((const int4*)(ib + OUT_PLANE))[qa];
        int4 uB = ((const int4*)(ib + OUT_PLANE))[qb];
        int4 vA = ((const int4*)(ib + 2 * OUT_PLANE))[qa];
        int4 vB = ((const int4*)(ib + 2 * OUT_PLANE))[qb];

        int ia[8] = {iA.x, iA.y, iA.z, iA.w, iB.x, iB.y, iB.z, iB.w};
        int ua[8] = {uA.x, uA.y, uA.z, uA.w, uB.x, uB.y, uB.z, uB.w};
        int va[8] = {vA.x, vA.y, vA.z, vA.w, vB.x, vB.y, vB.z, vB.w};

        float rr[8], gg[8], bb[8];
#pragma unroll
        for (int k = 0; k < 8; k++)
            lookup_px(ia[k], ua[k], va[k], srg, sb, tex, lut, b,
                      rr[k], gg[k], bb[k]);

        ((float4*)(ob))[qa]                 = make_float4(rr[0], rr[1], rr[2], rr[3]);
        ((float4*)(ob))[qb]                 = make_float4(rr[4], rr[5], rr[6], rr[7]);
        ((float4*)(ob + OUT_PLANE))[qa]     = make_float4(gg[0], gg[1], gg[2], gg[3]);
        ((float4*)(ob + OUT_PLANE))[qb]     = make_float4(gg[4], gg[5], gg[6], gg[7]);
        ((float4*)(ob + 2 * OUT_PLANE))[qa] = make_float4(bb[0], bb[1], bb[2], bb[3]);
        ((float4*)(ob + 2 * OUT_PLANE))[qb] = make_float4(bb[4], bb[5], bb[6], bb[7]);
    }
}

extern "C" void kernel_launch(void* const* d_in, const int* in_sizes, int n_in,
                              void* d_out, int out_size) {
    const float* tex = (const float*)d_in[0];   // [16,3,512,512] f32
    const int*   iuv = (const int*)d_in[1];     // [16,3,768,768] i32
    const float* lut = (const float*)d_in[2];   // [25,256,256,2] f32
    float* out = (float*)d_out;                 // [16,3,768,768] f32

    build_table<<<(BT_QUARTER + BT_THREADS - 1) / BT_THREADS, BT_THREADS>>>(tex, lut);

    {
        const int smem_bytes = PST_RG * 8 + PST_B * 4;  // 187,520 B
        // cudaFuncSetAttribute is host-side (not a stream op): capture-safe.
        cudaFuncSetAttribute(map_pixels,
                             cudaFuncAttributeMaxDynamicSharedMemorySize,
                             smem_bytes);
        map_pixels<<<NB * CTAS_PER_B, MAP_THREADS, smem_bytes>>>(tex, iuv, lut, out);
    }
}

// round 11
// speedup vs baseline: 1.0574x; 1.0574x over previous
#include <cuda_runtime.h>

// Problem shapes (fixed by the dataset)
#define NB 16        // batch
#define NC 3         // channels
#define TH 512       // tex H
#define TW 512       // tex W
#define OH 768       // out H
#define OW 768       // out W
#define NI 25        // lut dim 0 (part index)
#define LD 256       // lut dims 1,2
#define TD 25        // table coverage for vi/ui (data has values in [0,25))

#define TEX_PLANE (TH*TW)          // 262144
#define TEX_IMG   (NC*TEX_PLANE)   // 786432
#define OUT_PLANE (OH*OW)          // 589824
#define OUT_IMG   (NC*OUT_PLANE)   // 1769472
#define TBL_PER_B (NI*TD*TD)       // 15625
#define PSTRIDE   15628            // TBL_PER_B padded to /4 for float4 copies

#define CTAS_PER_B 9               // 589824 = 9 * 65536 -> 144 CTAs = one wave
#define QUADS_PER_CTA 16384        // 65536 pixels / 4
#define MAP_THREADS 1024

// Precomputed sample table, SoA: 3 planes of [B][PSTRIDE] floats (~3 MB, L2-resident)
__device__ float g_tab[3][NB * PSTRIDE];

// ---------------------------------------------------------------------------
// Variant A (map_pixels' fallback — branchy, exact R4/R9 form):
// bilinear grid-sample matching torch grid_sample (bilinear, zeros,
// align_corners=True).
__device__ __forceinline__ float3 sample_tex_branchy(const float* __restrict__ tex,
                                                     int b, float us, float vs) {
    float uI = us * 2.0f - 1.0f;
    float vI = (1.0f - vs) * 2.0f - 1.0f;
    float x = (uI + 1.0f) * 0.5f * (float)(TW - 1);
    float y = (vI + 1.0f) * 0.5f * (float)(TH - 1);
    float x0f = floorf(x);
    float y0f = floorf(y);
    float wx = x - x0f;
    float wy = y - y0f;
    int x0 = (int)x0f;
    int y0 = (int)y0f;

    const float* __restrict__ base = tex + (size_t)b * TEX_IMG;
    float r = 0.0f, g = 0.0f, bl = 0.0f;
#pragma unroll
    for (int dy = 0; dy < 2; dy++) {
#pragma unroll
        for (int dx = 0; dx < 2; dx++) {
            int xx = x0 + dx;
            int yy = y0 + dy;
            bool valid = (xx >= 0) & (xx < TW) & (yy >= 0) & (yy < TH);
            float w = (dy ? wy : (1.0f - wy)) * (dx ? wx : (1.0f - wx));
            if (valid) {
                int off = yy * TW + xx;
                r  += __ldg(base + off) * w;
                g  += __ldg(base + TEX_PLANE + off) * w;
                bl += __ldg(base + 2 * TEX_PLANE + off) * w;
            }
        }
    }
    return make_float3(r, g, bl);
}

// Variant B (build_table — branchless, exact R6/R9 form): loads always issue
// from clamped addresses; validity folded into the weight so ptxas can
// front-batch all 12 LDGs per entry.
__device__ __forceinline__ float3 sample_tex_nobranch(const float* __restrict__ tex,
                                                      int b, float us, float vs) {
    float uI = us * 2.0f - 1.0f;
    float vI = (1.0f - vs) * 2.0f - 1.0f;
    float x = (uI + 1.0f) * 0.5f * (float)(TW - 1);
    float y = (vI + 1.0f) * 0.5f * (float)(TH - 1);
    float x0f = floorf(x);
    float y0f = floorf(y);
    float wx = x - x0f;
    float wy = y - y0f;
    int x0 = (int)x0f;
    int y0 = (int)y0f;

    const float* __restrict__ base = tex + (size_t)b * TEX_IMG;
    float r = 0.0f, g = 0.0f, bl = 0.0f;

    float tr[4], tg[4], tb[4], wq[4];
#pragma unroll
    for (int dy = 0; dy < 2; dy++) {
#pragma unroll
        for (int dx = 0; dx < 2; dx++) {
            int k = dy * 2 + dx;
            int xx = x0 + dx;
            int yy = y0 + dy;
            bool valid = (xx >= 0) & (xx < TW) & (yy >= 0) & (yy < TH);
            float w = (dy ? wy : (1.0f - wy)) * (dx ? wx : (1.0f - wx));
            wq[k] = valid ? w : 0.0f;
            int off = min(max(yy, 0), TH - 1) * TW + min(max(xx, 0), TW - 1);
            tr[k] = __ldg(base + off);
            tg[k] = __ldg(base + TEX_PLANE + off);
            tb[k] = __ldg(base + 2 * TEX_PLANE + off);
        }
    }
#pragma unroll
    for (int k = 0; k < 4; k++) {
        r  += tr[k] * wq[k];
        g  += tg[k] * wq[k];
        bl += tb[k] * wq[k];
    }
    return make_float3(r, g, bl);
}

// Phase 1: build the (b, i, vi, ui) -> rgb SoA table. 4 entries per thread
// (grid-strided by quarter) so ~48 independent gathers overlap per thread.
#define BT_THREADS 256
#define BT_QUARTER (NB * TBL_PER_B / 4)      // 62500
__global__ void __launch_bounds__(BT_THREADS)
build_table(const float* __restrict__ tex, const float* __restrict__ lut) {
    int t = blockIdx.x * blockDim.x + threadIdx.x;
    if (t >= BT_QUARTER) return;

    int eb[4], er[4];
    float us[4], vs[4];
#pragma unroll
    for (int h = 0; h < 4; h++) {
        int e = t + h * BT_QUARTER;
        int b  = e / TBL_PER_B;
        int r  = e - b * TBL_PER_B;
        int i  = r / (TD * TD);
        int r2 = r - i * (TD * TD);
        int vi = r2 / TD;
        int ui = r2 - vi * TD;
        int lo = ((i * LD + vi) * LD + ui) * 2;
        us[h] = __ldg(lut + lo);
        vs[h] = __ldg(lut + lo + 1);
        eb[h] = b; er[h] = r;
    }
#pragma unroll
    for (int h = 0; h < 4; h++) {
        float3 c = sample_tex_nobranch(tex, eb[h], us[h], vs[h]);
        int o = eb[h] * PSTRIDE + er[h];
        g_tab[0][o] = c.x;
        g_tab[1][o] = c.y;
        g_tab[2][o] = c.z;
    }
}

// Phase 2: streaming pass with fp32 table slice staged in shared memory.
// 187.5 KB smem/CTA -> 1 CTA/SM, 144 CTAs = one full wave.
// Change vs R9: the in-table test is hoisted out of the per-pixel path --
// one branch per 8 pixels guards a straight-line block of 24 batched LDS.
__global__ void __launch_bounds__(MAP_THREADS, 1)
map_pixels(const float* __restrict__ tex,
           const int* __restrict__ iuv,
           const float* __restrict__ lut,
           float* __restrict__ out) {
    extern __shared__ float smem[];
    float* sr = smem;
    float* sg = smem + PSTRIDE;
    float* sb = smem + 2 * PSTRIDE;

    int b   = blockIdx.x / CTAS_PER_B;
    int sub = blockIdx.x - b * CTAS_PER_B;
    int tid = threadIdx.x;

    // Stage this batch's table slice into smem (float4 bulk copy).
#pragma unroll
    for (int c = 0; c < 3; c++) {
        const float4* src = (const float4*)&g_tab[c][b * PSTRIDE];
        float4* dst = (float4*)(smem + c * PSTRIDE);
        for (int t = tid; t < PSTRIDE / 4; t += MAP_THREADS)
            dst[t] = src[t];
    }
    __syncthreads();

    const int* __restrict__ ib = iuv + (size_t)b * OUT_IMG;
    float* __restrict__ ob = out + (size_t)b * OUT_IMG;
    const int q0 = sub * QUADS_PER_CTA;

    // 2 quads (8 pixels) per iteration: 6 front-batched int4 loads for MLP.
#pragma unroll
    for (int j = 0; j < QUADS_PER_CTA / (2 * MAP_THREADS); j++) {
        int qa = q0 + j * (2 * MAP_THREADS) + tid;
        int qb = qa + MAP_THREADS;

        int4 iA = ((const int4*)(ib))[qa];
        int4 iB = ((const int4*)(ib))[qb];
        int4 uA = ((const int4*)(ib + OUT_PLANE))[qa];
        int4 uB = ((const int4*)(ib + OUT_PLANE))[qb];
        int4 vA = ((const int4*)(ib + 2 * OUT_PLANE))[qa];
        int4 vB = ((const int4*)(ib + 2 * OUT_PLANE))[qb];

        int ia[8] = {iA.x, iA.y, iA.z, iA.w, iB.x, iB.y, iB.z, iB.w};
        int ua[8] = {uA.x, uA.y, uA.z, uA.w, uB.x, uB.y, uB.z, uB.w};
        int va[8] = {vA.x, vA.y, vA.z, vA.w, vB.x, vB.y, vB.z, vB.w};

        // Compute all 8 table indices + a combined fast-path predicate.
        // For int32 inputs, rint(clip(ua/255,0,1)*255) == clamp(ua,0,255).
        int idx[8];
        bool fast = true;
#pragma unroll
        for (int k = 0; k < 8; k++) {
            int i  = min(max(ia[k], 0), NI - 1);
            int ui = min(max(ua[k], 0), LD - 1);
            int vi = min(max(va[k], 0), LD - 1);
            fast = fast & (ui < TD) & (vi < TD);
            // index valid only when fast; clamp to table range for safety
            int uic = min(ui, TD - 1);
            int vic = min(vi, TD - 1);
            idx[k] = (i * TD + vic) * TD + uic;
        }

        float rr[8], gg[8], bb[8];
        if (fast) {
            // Straight-line: 24 independent LDS, batched by ptxas.
#pragma unroll
            for (int k = 0; k < 8; k++) rr[k] = sr[idx[k]];
#pragma unroll
            for (int k = 0; k < 8; k++) gg[k] = sg[idx[k]];
#pragma unroll
            for (int k = 0; k < 8; k++) bb[k] = sb[idx[k]];
        } else {
            // Cold mixed path: per-pixel, exact reference semantics.
#pragma unroll
            for (int k = 0; k < 8; k++) {
                int i  = min(max(ia[k], 0), NI - 1);
                int ui = min(max(ua[k], 0), LD - 1);
                int vi = min(max(va[k], 0), LD - 1);
                if (ui < TD && vi < TD) {
                    int id = (i * TD + vi) * TD + ui;
                    rr[k] = sr[id]; gg[k] = sg[id]; bb[k] = sb[id];
                } else {
                    int lo = ((i * LD + vi) * LD + ui) * 2;
                    float3 c = sample_tex_branchy(tex, b, lut[lo], lut[lo + 1]);
                    rr[k] = c.x; gg[k] = c.y; bb[k] = c.z;
                }
            }
        }

        ((float4*)(ob))[qa]                 = make_float4(rr[0], rr[1], rr[2], rr[3]);
        ((float4*)(ob))[qb]                 = make_float4(rr[4], rr[5], rr[6], rr[7]);
        ((float4*)(ob + OUT_PLANE))[qa]     = make_float4(gg[0], gg[1], gg[2], gg[3]);
        ((float4*)(ob + OUT_PLANE))[qb]     = make_float4(gg[4], gg[5], gg[6], gg[7]);
        ((float4*)(ob + 2 * OUT_PLANE))[qa] = make_float4(bb[0], bb[1], bb[2], bb[3]);
        ((float4*)(ob + 2 * OUT_PLANE))[qb] = make_float4(bb[4], bb[5], bb[6], bb[7]);
    }
}

extern "C" void kernel_launch(void* const* d_in, const int* in_sizes, int n_in,
                              void* d_out, int out_size) {
    const float* tex = (const float*)d_in[0];   // [16,3,512,512] f32
    const int*   iuv = (const int*)d_in[1];     // [16,3,768,768] i32
    const float* lut = (const float*)d_in[2];   // [25,256,256,2] f32
    float* out = (float*)d_out;                 // [16,3,768,768] f32

    build_table<<<(BT_QUARTER + BT_THREADS - 1) / BT_THREADS, BT_THREADS>>>(tex, lut);

    {
        const int smem_bytes = 3 * PSTRIDE * (int)sizeof(float);  // 187,536 B
        // cudaFuncSetAttribute is host-side (not a stream op): capture-safe.
        cudaFuncSetAttribute(map_pixels,
                             cudaFuncAttributeMaxDynamicSharedMemorySize,
                             smem_bytes);
        map_pixels<<<NB * CTAS_PER_B, MAP_THREADS, smem_bytes>>>(tex, iuv, lut, out);
    }
}